// round 9
// baseline (speedup 1.0000x reference)
#include <cuda_runtime.h>
#include <cuda_bf16.h>
#include <cstdint>

// out[b, 0:64] = full_input[b, idx[b]*64 : (idx[b]+1)*64]
// B = 262144, OUTPUT_DIM = 64, NB_CTRL_SIG = 16, fp32.
// v7: LTS-bound regime -> minimize wavefronts + maximize steady-state L2
// read residency. 32-B evict_last loads (pins 64 MB read set in 126 MB L2
// across graph replays), 32-B .cs streaming stores (don't evict the reads),
// 8 rows per thread (deep MLP), 512-thread CTAs (half the CTA churn).

static constexpr int BATCH      = 262144;
static constexpr int ROW_BYTES  = 4096;   // input row: 1024 floats
static constexpr int BLK_BYTES  = 256;    // selected block: 64 floats
static constexpr int LANES      = 8;      // 8 lanes x 32 B per block
static constexpr int UNROLL     = 8;      // rows per thread
static constexpr int THREADS    = 512;

struct V32 { unsigned long long a, b, c, d; };  // 32 bytes

__device__ __forceinline__ V32 ldg_persist32(const void* p) {
    V32 v;
    asm volatile("ld.global.nc.L2::evict_last.v4.b64 {%0,%1,%2,%3}, [%4];"
                 : "=l"(v.a), "=l"(v.b), "=l"(v.c), "=l"(v.d) : "l"(p));
    return v;
}

__device__ __forceinline__ void stg_stream32(void* p, V32 v) {
    asm volatile("st.global.cs.v4.b64 [%0], {%1,%2,%3,%4};"
                 :: "l"(p), "l"(v.a), "l"(v.b), "l"(v.c), "l"(v.d) : "memory");
}

__global__ void __launch_bounds__(THREADS) multiplexer_gather_v7(
    const char* __restrict__ in,       // [BATCH * 4096] bytes
    const int4* __restrict__ idx4,     // [BATCH/4] int4 view of indices
    char*       __restrict__ out)      // [BATCH * 256] bytes
{
    const uint32_t t    = blockIdx.x * blockDim.x + threadIdx.x;
    const uint32_t g    = t >> 3;            // group of 8 consecutive rows
    const uint32_t lane = t & 7u;            // 32-B slot within 256-B block
    const uint32_t row0 = g * UNROLL;

    // Two vector index loads per group (8-way broadcast within lane group).
    const int4 ia = __ldg(&idx4[2 * g + 0]); // rows row0..row0+3
    const int4 ib = __ldg(&idx4[2 * g + 1]); // rows row0+4..row0+7

    int idx[UNROLL] = { ia.x, ia.y, ia.z, ia.w, ib.x, ib.y, ib.z, ib.w };

    // 8 independent 32-B gathers, L2-pinned (identical set every replay).
    V32 v[UNROLL];
    #pragma unroll
    for (int u = 0; u < UNROLL; u++) {
        const char* src = in + (size_t)(row0 + u) * ROW_BYTES
                             + (uint32_t)idx[u] * BLK_BYTES + lane * 32u;
        v[u] = ldg_persist32(src);
    }

    // 8 coalesced 32-B streaming stores (contiguous 256 B per lane group).
    #pragma unroll
    for (int u = 0; u < UNROLL; u++) {
        stg_stream32(out + (size_t)(row0 + u) * BLK_BYTES + lane * 32u, v[u]);
    }
}

extern "C" void kernel_launch(void* const* d_in, const int* in_sizes, int n_in,
                              void* d_out, int out_size) {
    const char* in   = (const char*)d_in[0];
    const int4* idx4 = (const int4*)d_in[1];
    char*       out  = (char*)d_out;

    const int total_threads = BATCH * LANES / UNROLL;   // 262144
    const int blocks = total_threads / THREADS;         // 512 CTAs
    multiplexer_gather_v7<<<blocks, THREADS>>>(in, idx4, out);
}

// round 10
// speedup vs baseline: 1.4332x; 1.4332x over previous
#include <cuda_runtime.h>
#include <cuda_bf16.h>
#include <cstdint>

// out[b, 0:64] = full_input[b, idx[b]*64 : (idx[b]+1)*64]
// B = 262144, OUTPUT_DIM = 64, NB_CTRL_SIG = 16, fp32.
// v8 = v3 (best: 8 rows/thread, 2x int4 idx loads, 8 independent LDG.128)
//  + 128-thread CTAs (finer wave balance across 148 SMs)
//  + .cs streaming stores (protect L2 read residency across graph replays).

static constexpr int BATCH = 262144;
static constexpr int IN_ROW_VEC = 256;   // float4 per input row (1024 floats)
static constexpr int VEC_PER_ROW = 16;   // float4 per output row (64 floats)
static constexpr int UNROLL = 8;         // rows per thread
static constexpr int THREADS = 128;

__device__ __forceinline__ void stg_stream(float4* p, float4 v) {
    asm volatile("st.global.cs.v4.f32 [%0], {%1,%2,%3,%4};"
                 :: "l"(p), "f"(v.x), "f"(v.y), "f"(v.z), "f"(v.w) : "memory");
}

__global__ void __launch_bounds__(THREADS) multiplexer_gather_v8(
    const float4* __restrict__ in,       // [BATCH, 256] float4
    const int4*   __restrict__ idx4,     // [BATCH/4] int4 view of indices
    float4*       __restrict__ out)      // [BATCH*16] float4
{
    const uint32_t t    = blockIdx.x * blockDim.x + threadIdx.x;
    const uint32_t g    = t >> 4;        // group of 8 consecutive rows
    const uint32_t lane = t & 15u;       // float4 slot within the 64-float block
    const uint32_t row0 = g * UNROLL;

    // Two vector index loads (16-way broadcast within lane group).
    const int4 ia = __ldg(&idx4[2 * g + 0]);   // rows row0..row0+3
    const int4 ib = __ldg(&idx4[2 * g + 1]);   // rows row0+4..row0+7

    int idx[UNROLL] = { ia.x, ia.y, ia.z, ia.w, ib.x, ib.y, ib.z, ib.w };

    // 8 independent data loads -> deep MLP.
    float4 v[UNROLL];
    #pragma unroll
    for (int u = 0; u < UNROLL; u++) {
        const uint32_t row = row0 + u;
        v[u] = __ldg(&in[(size_t)row * IN_ROW_VEC
                         + (uint32_t)idx[u] * VEC_PER_ROW + lane]);
    }

    // 8 coalesced streaming stores (evict-first: keep L2 for the read set).
    #pragma unroll
    for (int u = 0; u < UNROLL; u++) {
        stg_stream(&out[(size_t)(row0 + u) * VEC_PER_ROW + lane], v[u]);
    }
}

extern "C" void kernel_launch(void* const* d_in, const int* in_sizes, int n_in,
                              void* d_out, int out_size) {
    const float4* in   = (const float4*)d_in[0];
    const int4*   idx4 = (const int4*)d_in[1];
    float4*       out  = (float4*)d_out;

    const int total_threads = BATCH * VEC_PER_ROW / UNROLL;  // 524288
    const int blocks = total_threads / THREADS;              // 4096 CTAs
    multiplexer_gather_v8<<<blocks, THREADS>>>(in, idx4, out);
}